// round 5
// baseline (speedup 1.0000x reference)
#include <cuda_runtime.h>
#include <math.h>

typedef unsigned long long ull;

#define NB 128
#define UNITS 1024
#define BATCH 32
#define TT 512
#define IND 512

// ---------------- static device scratch (allocation-free) ----------------
__device__ float g_xp[(size_t)BATCH * TT * 4 * UNITS];  // [(b*512+t)][4096]
__device__ float g_h[2][UNITS * BATCH];                 // [unit][batch], double buffered
__device__ float g_c[UNITS * BATCH];                    // cell state [unit][batch]

// ---------------- f32x2 helpers (FFMA2 = 2x fp32 FMA rate on sm_103a) -----
__device__ __forceinline__ void fma2(ull& d, ull a, ull b) {
    asm("fma.rn.f32x2 %0, %1, %2, %0;" : "+l"(d) : "l"(a), "l"(b));
}
__device__ __forceinline__ ull splat2(float x) {
    ull r; asm("mov.b64 %0, {%1, %1};" : "=l"(r) : "f"(x)); return r;
}
__device__ __forceinline__ void unpack2(ull v, float& lo, float& hi) {
    asm("mov.b64 {%0, %1}, %2;" : "=f"(lo), "=f"(hi) : "l"(v));
}

// ===================== init: zero h0 and c0 ==============================
__global__ void init_kernel() {
    int i = blockIdx.x * blockDim.x + threadIdx.x;
    int n = UNITS * BATCH;
    for (int j = i; j < n; j += gridDim.x * blockDim.x) {
        g_h[0][j] = 0.0f;
        g_c[j] = 0.0f;
    }
}

// ============ phase 1: g_xp = inputs @ W + b  (FFMA2 SGEMM) ===============
// A [16384 x 512], W [512 x 4096]. Tile 128x128xK16, 256 threads, 8x8/thread.
__global__ __launch_bounds__(256) void xproj_kernel(const float* __restrict__ A,
                                                    const float* __restrict__ W,
                                                    const float* __restrict__ bias) {
    __shared__ float Asm[16][132];   // transposed A tile [k][row], padded
    __shared__ ull   Bsm[16][128];   // W tile, values pre-splatted

    const int tid = threadIdx.x;
    const int bn = blockIdx.x << 7;
    const int bm = blockIdx.y << 7;
    const int tx = tid & 15;
    const int ty = tid >> 4;
    const int row0 = ty << 3;
    const int cbase = tx << 1;       // column pairs at cbase + q*32

    ull acc[4][8];
#pragma unroll
    for (int q = 0; q < 4; ++q) {
        ull b0 = splat2(bias[bn + cbase + (q << 5)]);
        ull b1 = splat2(bias[bn + cbase + (q << 5) + 1]);
#pragma unroll
        for (int rp = 0; rp < 4; ++rp) {
            acc[rp][(q << 1)]     = b0;
            acc[rp][(q << 1) + 1] = b1;
        }
    }

    for (int k0 = 0; k0 < IND; k0 += 16) {
#pragma unroll
        for (int r = 0; r < 2; ++r) {          // A tile 128x16, transposed
            int i4 = tid + (r << 8);
            int row = i4 >> 2, kq = (i4 & 3) << 2;
            float4 v = *(const float4*)&A[(size_t)(bm + row) * IND + k0 + kq];
            Asm[kq + 0][row] = v.x;
            Asm[kq + 1][row] = v.y;
            Asm[kq + 2][row] = v.z;
            Asm[kq + 3][row] = v.w;
        }
#pragma unroll
        for (int r = 0; r < 2; ++r) {          // W tile 16x128, splat-stored
            int i4 = tid + (r << 8);
            int kr = i4 >> 5, n4 = (i4 & 31) << 2;
            float4 v = *(const float4*)&W[(size_t)(k0 + kr) * 4096 + bn + n4];
            *(ulonglong2*)&Bsm[kr][n4]     = make_ulonglong2(splat2(v.x), splat2(v.y));
            *(ulonglong2*)&Bsm[kr][n4 + 2] = make_ulonglong2(splat2(v.z), splat2(v.w));
        }
        __syncthreads();
#pragma unroll
        for (int k = 0; k < 16; ++k) {
            ull ap[4];
#pragma unroll
            for (int rp = 0; rp < 4; ++rp)
                ap[rp] = *(const ull*)&Asm[k][row0 + (rp << 1)];
            ulonglong2 bq[4];
#pragma unroll
            for (int q = 0; q < 4; ++q)
                bq[q] = *(const ulonglong2*)&Bsm[k][cbase + (q << 5)];
#pragma unroll
            for (int rp = 0; rp < 4; ++rp)
#pragma unroll
                for (int q = 0; q < 4; ++q) {
                    fma2(acc[rp][(q << 1)],     ap[rp], bq[q].x);
                    fma2(acc[rp][(q << 1) + 1], ap[rp], bq[q].y);
                }
        }
        __syncthreads();
    }
#pragma unroll
    for (int rp = 0; rp < 4; ++rp) {
        size_t r0 = (size_t)(bm + row0 + (rp << 1)) * 4096 + bn + cbase;
        size_t r1 = r0 + 4096;
#pragma unroll
        for (int q = 0; q < 4; ++q) {
            float l0, h0, l1, h1;
            unpack2(acc[rp][(q << 1)],     l0, h0);
            unpack2(acc[rp][(q << 1) + 1], l1, h1);
            *(float2*)&g_xp[r0 + (q << 5)] = make_float2(l0, l1);
            *(float2*)&g_xp[r1 + (q << 5)] = make_float2(h0, h1);
        }
    }
}

// ============ phase 2: one launch per timestep (no cross-block sync) ======
// 128 blocks x 256 threads. Block owns 8 units x 4 gates = 32 gate-columns.
// smem column c <-> global column: gate = c&3, unit_in_blk = c>>2
//   colg(c) = (c&3)*1024 + blk*8 + (c>>2)
// Thread (wg, b): owns smem cols wg*4..wg*4+3 = gates i,f,g,o of unit blk*8+wg
//   for batch lane b. a0 = (z_i, z_f), a1 = (z_g, z_o). No z exchange needed.
// smem: Us[2][256*32] (64K) + hs[2][256*32] (64K) = 128K, 1 block/SM.
#define STEP_SMEM (2 * 8192 * 4 + 2 * 8192 * 4)

__global__ void __launch_bounds__(256) step_kernel(const float* __restrict__ U,
                                                   float* __restrict__ out,
                                                   int t) {
    extern __shared__ unsigned char sm[];
    float* Us = (float*)sm;                 // [2][8192]
    float* hs = (float*)(sm + 65536);       // [2][8192]

    const int tid = threadIdx.x;
    const int blk = blockIdx.x;
    const int b   = tid & 31;
    const int wg  = tid >> 5;
    const int c0  = wg << 2;
    const int u   = (blk << 3) + wg;        // global unit
    const int cur = t & 1;

    const float* hsrc = g_h[cur];

    // staging identity: this thread stages U column cU, rows (tid>>5)+8*it
    const int cU = tid & 31;
    const size_t colgU = (size_t)((cU & 3) << 10) + (blk << 3) + (cU >> 2);
    const int krow0 = tid >> 5;

    // ---- prefetch xp for this thread's (u, b) : 4 gates ----
    const size_t btrow = ((size_t)((b << 9) | t)) << 12;
    float xpi = __ldg(&g_xp[btrow + u]);
    float xpf = __ldg(&g_xp[btrow + 1024 + u]);
    float xpg = __ldg(&g_xp[btrow + 2048 + u]);
    float xpo = __ldg(&g_xp[btrow + 3072 + u]);

    // ---- stage chunk 0 (U rows 0..255, h rows 0..255) ----
    float  ur[32];
    float4 hr[8];
#pragma unroll
    for (int it = 0; it < 32; ++it)
        ur[it] = __ldg(&U[((size_t)(krow0 + (it << 3)) << 12) + colgU]);
#pragma unroll
    for (int it = 0; it < 8; ++it)
        hr[it] = __ldg((const float4*)&hsrc[(tid + (it << 8)) << 2]);
#pragma unroll
    for (int it = 0; it < 32; ++it)
        Us[((krow0 + (it << 3)) << 5) + cU] = ur[it];
#pragma unroll
    for (int it = 0; it < 8; ++it)
        *(float4*)&hs[(tid + (it << 8)) << 2] = hr[it];
    __syncthreads();

    ull a0 = 0ull, a1 = 0ull;

#pragma unroll 1
    for (int ch = 0; ch < 4; ++ch) {
        // prefetch next chunk into registers (overlaps compute below)
        if (ch < 3) {
            const int kb = (ch + 1) << 8;
#pragma unroll
            for (int it = 0; it < 32; ++it)
                ur[it] = __ldg(&U[((size_t)(kb + krow0 + (it << 3)) << 12) + colgU]);
#pragma unroll
            for (int it = 0; it < 8; ++it)
                hr[it] = __ldg((const float4*)&hsrc[(kb << 5) + ((tid + (it << 8)) << 2)]);
        }
        // compute this chunk: LDS.32(h) + MOV(splat) + LDS.128(U bcast) + 2 FFMA2
        {
            const float* hp = hs + (ch & 1) * 8192 + b;
            const float* up = Us + (ch & 1) * 8192 + c0;
#pragma unroll 16
            for (int kk = 0; kk < 256; ++kk) {
                float hv = hp[kk << 5];
                ull h2 = splat2(hv);
                ulonglong2 uu = *(const ulonglong2*)(up + (kk << 5));
                fma2(a0, uu.x, h2);
                fma2(a1, uu.y, h2);
            }
        }
        // store prefetched chunk into the other buffer
        if (ch < 3) {
            float* ud = Us + ((ch + 1) & 1) * 8192;
            float* hd = hs + ((ch + 1) & 1) * 8192;
#pragma unroll
            for (int it = 0; it < 32; ++it)
                ud[((krow0 + (it << 3)) << 5) + cU] = ur[it];
#pragma unroll
            for (int it = 0; it < 8; ++it)
                *(float4*)&hd[(tid + (it << 8)) << 2] = hr[it];
        }
        __syncthreads();
    }

    // ---- pointwise: this thread holds all 4 gates of (u, b) ----
    float zi, zf, zg, zo;
    unpack2(a0, zi, zf);
    unpack2(a1, zg, zo);
    zi += xpi; zf += xpf; zg += xpg; zo += xpo;

    float ig = 1.0f / (1.0f + __expf(-zi));
    float fg = 1.0f / (1.0f + __expf(-zf));
    float gg = tanhf(zg);
    float og = 1.0f / (1.0f + __expf(-zo));

    float c = fg * g_c[(u << 5) + b] + ig * gg;
    g_c[(u << 5) + b] = c;
    float h = og * tanhf(c);

    g_h[cur ^ 1][(u << 5) + b] = h;
    out[(((size_t)((b << 9) | t)) << 10) + u] = h;
}

// ========================= launcher ======================================
extern "C" void kernel_launch(void* const* d_in, const int* in_sizes, int n_in,
                              void* d_out, int out_size) {
    const float* inputs = (const float*)d_in[0];
    const float* W      = (const float*)d_in[1];
    const float* U      = (const float*)d_in[2];
    const float* bias   = (const float*)d_in[3];
    float* out = (float*)d_out;

    cudaFuncSetAttribute(step_kernel,
                         cudaFuncAttributeMaxDynamicSharedMemorySize, STEP_SMEM);

    init_kernel<<<64, 256>>>();
    dim3 g1(32, 128);
    xproj_kernel<<<g1, 256>>>(inputs, W, bias);
    for (int t = 0; t < TT; ++t)
        step_kernel<<<NB, 256, STEP_SMEM>>>(U, out, t);
}

// round 6
// speedup vs baseline: 1.1896x; 1.1896x over previous
#include <cuda_runtime.h>
#include <math.h>

typedef unsigned long long ull;

#define NB 128
#define UNITS 1024
#define BATCH 32
#define TT 512
#define IND 512

// ---------------- static device scratch (allocation-free) ----------------
__device__ float g_xp[(size_t)BATCH * TT * 4 * UNITS];  // [(b*512+t)][4096]
__device__ float g_h[2][UNITS * BATCH];                 // [unit][batch], double buffered
__device__ float g_c[UNITS * BATCH];                    // cell state [unit][batch]

// ---------------- f32x2 helpers (FFMA2 = 2x fp32 FMA rate on sm_103a) -----
__device__ __forceinline__ void fma2(ull& d, ull a, ull b) {
    asm("fma.rn.f32x2 %0, %1, %2, %0;" : "+l"(d) : "l"(a), "l"(b));
}
__device__ __forceinline__ void add2(ull& d, ull a) {
    asm("add.rn.f32x2 %0, %0, %1;" : "+l"(d) : "l"(a));
}
__device__ __forceinline__ ull splat2(float x) {
    ull r; asm("mov.b64 %0, {%1, %1};" : "=l"(r) : "f"(x)); return r;
}
__device__ __forceinline__ void unpack2(ull v, float& lo, float& hi) {
    asm("mov.b64 {%0, %1}, %2;" : "=f"(lo), "=f"(hi) : "l"(v));
}

// ===================== init: zero h0 and c0 ==============================
__global__ void init_kernel() {
    int i = blockIdx.x * blockDim.x + threadIdx.x;
    int n = UNITS * BATCH;
    for (int j = i; j < n; j += gridDim.x * blockDim.x) {
        g_h[0][j] = 0.0f;
        g_c[j] = 0.0f;
    }
}

// ============ phase 1: g_xp = inputs @ W + b  (FFMA2 SGEMM) ===============
__global__ __launch_bounds__(256) void xproj_kernel(const float* __restrict__ A,
                                                    const float* __restrict__ W,
                                                    const float* __restrict__ bias) {
    __shared__ float Asm[16][132];
    __shared__ ull   Bsm[16][128];

    const int tid = threadIdx.x;
    const int bn = blockIdx.x << 7;
    const int bm = blockIdx.y << 7;
    const int tx = tid & 15;
    const int ty = tid >> 4;
    const int row0 = ty << 3;
    const int cbase = tx << 1;

    ull acc[4][8];
#pragma unroll
    for (int q = 0; q < 4; ++q) {
        ull b0 = splat2(bias[bn + cbase + (q << 5)]);
        ull b1 = splat2(bias[bn + cbase + (q << 5) + 1]);
#pragma unroll
        for (int rp = 0; rp < 4; ++rp) {
            acc[rp][(q << 1)]     = b0;
            acc[rp][(q << 1) + 1] = b1;
        }
    }

    for (int k0 = 0; k0 < IND; k0 += 16) {
#pragma unroll
        for (int r = 0; r < 2; ++r) {
            int i4 = tid + (r << 8);
            int row = i4 >> 2, kq = (i4 & 3) << 2;
            float4 v = *(const float4*)&A[(size_t)(bm + row) * IND + k0 + kq];
            Asm[kq + 0][row] = v.x;
            Asm[kq + 1][row] = v.y;
            Asm[kq + 2][row] = v.z;
            Asm[kq + 3][row] = v.w;
        }
#pragma unroll
        for (int r = 0; r < 2; ++r) {
            int i4 = tid + (r << 8);
            int kr = i4 >> 5, n4 = (i4 & 31) << 2;
            float4 v = *(const float4*)&W[(size_t)(k0 + kr) * 4096 + bn + n4];
            *(ulonglong2*)&Bsm[kr][n4]     = make_ulonglong2(splat2(v.x), splat2(v.y));
            *(ulonglong2*)&Bsm[kr][n4 + 2] = make_ulonglong2(splat2(v.z), splat2(v.w));
        }
        __syncthreads();
#pragma unroll
        for (int k = 0; k < 16; ++k) {
            ull ap[4];
#pragma unroll
            for (int rp = 0; rp < 4; ++rp)
                ap[rp] = *(const ull*)&Asm[k][row0 + (rp << 1)];
            ulonglong2 bq[4];
#pragma unroll
            for (int q = 0; q < 4; ++q)
                bq[q] = *(const ulonglong2*)&Bsm[k][cbase + (q << 5)];
#pragma unroll
            for (int rp = 0; rp < 4; ++rp)
#pragma unroll
                for (int q = 0; q < 4; ++q) {
                    fma2(acc[rp][(q << 1)],     ap[rp], bq[q].x);
                    fma2(acc[rp][(q << 1) + 1], ap[rp], bq[q].y);
                }
        }
        __syncthreads();
    }
#pragma unroll
    for (int rp = 0; rp < 4; ++rp) {
        size_t r0 = (size_t)(bm + row0 + (rp << 1)) * 4096 + bn + cbase;
        size_t r1 = r0 + 4096;
#pragma unroll
        for (int q = 0; q < 4; ++q) {
            float l0, h0, l1, h1;
            unpack2(acc[rp][(q << 1)],     l0, h0);
            unpack2(acc[rp][(q << 1) + 1], l1, h1);
            *(float2*)&g_xp[r0 + (q << 5)] = make_float2(l0, l1);
            *(float2*)&g_xp[r1 + (q << 5)] = make_float2(h0, h1);
        }
    }
}

// ============ phase 2: one launch per timestep ============================
// 128 blocks x 512 threads (16 warps). Block owns 8 units x 4 gates.
// smem col c: unit = c>>2, gate = c&3; colg(c) = (c&3)*1024 + blk*8 + (c>>2).
// 8 k-groups of 2 warps; group gg handles k = p*256 + gg*32 + j over 4 phases.
// Warp (gg, w2): w2 selects units w2*4..w2*4+3 (16 smem cols); lanes = batch.
// Thread accumulates 8 ull: a[2q]=(zi,zf), a[2q+1]=(zg,zo) of unit w2*4+q.
// smem: Us[2][256*32] 64K | hs[2][256*32] 64K | zred ull[8][8][32][2] 32K
#define STEP_SMEM (65536 + 65536 + 32768)

__global__ void __launch_bounds__(512) step_kernel(const float* __restrict__ U,
                                                   float* __restrict__ out,
                                                   int t) {
    extern __shared__ unsigned char sm[];
    float* Us  = (float*)sm;                  // [2][8192]
    float* hs  = (float*)(sm + 65536);        // [2][8192]
    ull*   zred = (ull*)(sm + 131072);        // [gg][unit][b][2]

    const int tid = threadIdx.x;
    const int blk = blockIdx.x;
    const int b   = tid & 31;
    const int w2  = (tid >> 5) & 1;
    const int gg  = tid >> 6;
    const int cu  = w2 << 4;                  // smem col base (16 cols)
    const int cur = t & 1;

    const float* hsrc = g_h[cur];

    // staging identity: col sc, rows sr + 16*it (within a 256-row phase)
    const int sc = tid & 31;
    const int sr = tid >> 5;                  // 0..15
    const size_t colg = (size_t)((sc & 3) << 10) + (blk << 3) + (sc >> 2);

    // xp prefetch for the reduction threads (tid<256: (unit uf, batch bf))
    float xpi = 0.f, xpf = 0.f, xpg = 0.f, xpo = 0.f;
    if (tid < 256) {
        const int uf = tid >> 5, bf = tid & 31;
        const int u = (blk << 3) + uf;
        const size_t btrow = ((size_t)((bf << 9) | t)) << 12;
        xpi = __ldg(&g_xp[btrow + u]);
        xpf = __ldg(&g_xp[btrow + 1024 + u]);
        xpg = __ldg(&g_xp[btrow + 2048 + u]);
        xpo = __ldg(&g_xp[btrow + 3072 + u]);
    }

    ull a[8];
#pragma unroll
    for (int q = 0; q < 8; ++q) a[q] = 0ull;

    float  ur[16];
    float4 hr[4];

    // ---- stage phase 0 ----
#pragma unroll
    for (int it = 0; it < 16; ++it)
        ur[it] = __ldg(&U[((size_t)(sr + (it << 4)) << 12) + colg]);
#pragma unroll
    for (int it = 0; it < 4; ++it)
        hr[it] = __ldg((const float4*)&hsrc[(tid + (it << 9)) << 2]);
#pragma unroll
    for (int it = 0; it < 16; ++it)
        Us[((sr + (it << 4)) << 5) + sc] = ur[it];
#pragma unroll
    for (int it = 0; it < 4; ++it)
        *(float4*)&hs[(tid + (it << 9)) << 2] = hr[it];
    __syncthreads();

#pragma unroll 1
    for (int p = 0; p < 4; ++p) {
        const int buf = p & 1;
        // prefetch next phase into registers (overlaps compute)
        if (p < 3) {
            const int kb = (p + 1) << 8;
#pragma unroll
            for (int it = 0; it < 16; ++it)
                ur[it] = __ldg(&U[((size_t)(kb + sr + (it << 4)) << 12) + colg]);
#pragma unroll
            for (int it = 0; it < 4; ++it)
                hr[it] = __ldg((const float4*)&hsrc[((kb << 5) + ((tid + (it << 9)) << 2))]);
        }
        // compute this thread's 32-k slice of the phase
        {
            const float* up = Us + (buf << 13) + cu;
            const float* hp = hs + (buf << 13) + b;
            const int r0 = gg << 5;
#pragma unroll
            for (int j = 0; j < 32; ++j) {
                const int roff = (r0 + j) << 5;
                ull h2 = splat2(hp[roff]);
                ulonglong2 u0 = *(const ulonglong2*)(up + roff);
                ulonglong2 u1 = *(const ulonglong2*)(up + roff + 4);
                ulonglong2 u2 = *(const ulonglong2*)(up + roff + 8);
                ulonglong2 u3 = *(const ulonglong2*)(up + roff + 12);
                fma2(a[0], u0.x, h2); fma2(a[1], u0.y, h2);
                fma2(a[2], u1.x, h2); fma2(a[3], u1.y, h2);
                fma2(a[4], u2.x, h2); fma2(a[5], u2.y, h2);
                fma2(a[6], u3.x, h2); fma2(a[7], u3.y, h2);
            }
        }
        // store prefetched phase into the other buffer
        if (p < 3) {
            float* ud = Us + ((buf ^ 1) << 13);
            float* hd = hs + ((buf ^ 1) << 13);
#pragma unroll
            for (int it = 0; it < 16; ++it)
                ud[((sr + (it << 4)) << 5) + sc] = ur[it];
#pragma unroll
            for (int it = 0; it < 4; ++it)
                *(float4*)&hd[(tid + (it << 9)) << 2] = hr[it];
        }
        __syncthreads();
    }

    // ---- write split-K partials ----
#pragma unroll
    for (int q = 0; q < 4; ++q) {
        const int u8 = (w2 << 2) + q;                 // unit in block
        *(ulonglong2*)&zred[((((gg << 3) | u8) << 5) | b) << 1] =
            make_ulonglong2(a[(q << 1)], a[(q << 1) + 1]);
    }
    __syncthreads();

    // ---- reduce + pointwise (first 256 threads: (unit uf, batch bf)) ----
    if (tid < 256) {
        const int uf = tid >> 5, bf = tid & 31;
        ull s0 = 0ull, s1 = 0ull;
#pragma unroll
        for (int g8 = 0; g8 < 8; ++g8) {
            ulonglong2 v = *(const ulonglong2*)&zred[((((g8 << 3) | uf) << 5) | bf) << 1];
            add2(s0, v.x);
            add2(s1, v.y);
        }
        float zi, zf, zg, zo;
        unpack2(s0, zi, zf);
        unpack2(s1, zg, zo);
        zi += xpi; zf += xpf; zg += xpg; zo += xpo;

        float ig = 1.0f / (1.0f + __expf(-zi));
        float fg = 1.0f / (1.0f + __expf(-zf));
        float gv = tanhf(zg);
        float og = 1.0f / (1.0f + __expf(-zo));

        const int u = (blk << 3) + uf;
        float c = fg * g_c[(u << 5) + bf] + ig * gv;
        g_c[(u << 5) + bf] = c;
        float h = og * tanhf(c);

        g_h[cur ^ 1][(u << 5) + bf] = h;
        out[(((size_t)((bf << 9) | t)) << 10) + u] = h;
    }
}

// ========================= launcher ======================================
extern "C" void kernel_launch(void* const* d_in, const int* in_sizes, int n_in,
                              void* d_out, int out_size) {
    const float* inputs = (const float*)d_in[0];
    const float* W      = (const float*)d_in[1];
    const float* U      = (const float*)d_in[2];
    const float* bias   = (const float*)d_in[3];
    float* out = (float*)d_out;

    cudaFuncSetAttribute(step_kernel,
                         cudaFuncAttributeMaxDynamicSharedMemorySize, STEP_SMEM);

    init_kernel<<<64, 256>>>();
    dim3 g1(32, 128);
    xproj_kernel<<<g1, 256>>>(inputs, W, bias);
    for (int t = 0; t < TT; ++t)
        step_kernel<<<NB, 512, STEP_SMEM>>>(U, out, t);
}

// round 7
// speedup vs baseline: 1.4094x; 1.1848x over previous
#include <cuda_runtime.h>
#include <math.h>

typedef unsigned long long ull;

#define NB 128
#define UNITS 1024
#define BATCH 32
#define TT 512
#define IND 512

// ---------------- static device scratch (allocation-free) ----------------
__device__ float    g_xp[(size_t)BATCH * TT * 4 * UNITS];  // [(b*512+t)][4096]
__device__ float    g_h[2][UNITS * BATCH];                 // [unit][batch], double buffered
__device__ unsigned g_bar;

// ---------------- f32x2 helpers (FFMA2 = 2x fp32 FMA rate on sm_103a) -----
__device__ __forceinline__ void fma2(ull& d, ull a, ull b) {
    asm("fma.rn.f32x2 %0, %1, %2, %0;" : "+l"(d) : "l"(a), "l"(b));
}
__device__ __forceinline__ void add2(ull& d, ull a) {
    asm("add.rn.f32x2 %0, %0, %1;" : "+l"(d) : "l"(a));
}
__device__ __forceinline__ ull splat2(float x) {
    ull r; asm("mov.b64 %0, {%1, %1};" : "=l"(r) : "f"(x)); return r;
}
__device__ __forceinline__ void unpack2(ull v, float& lo, float& hi) {
    asm("mov.b64 {%0, %1}, %2;" : "=f"(lo), "=f"(hi) : "l"(v));
}

// ===================== init: zero h0 + barrier ===========================
__global__ void init_kernel() {
    int i = blockIdx.x * blockDim.x + threadIdx.x;
    if (i == 0) g_bar = 0u;
    for (int j = i; j < UNITS * BATCH; j += gridDim.x * blockDim.x)
        g_h[0][j] = 0.0f;
}

// ============ phase 1: g_xp = inputs @ W + b  (FFMA2 SGEMM) ===============
__global__ __launch_bounds__(256) void xproj_kernel(const float* __restrict__ A,
                                                    const float* __restrict__ W,
                                                    const float* __restrict__ bias) {
    __shared__ float Asm[16][132];
    __shared__ ull   Bsm[16][128];

    const int tid = threadIdx.x;
    const int bn = blockIdx.x << 7;
    const int bm = blockIdx.y << 7;
    const int tx = tid & 15;
    const int ty = tid >> 4;
    const int row0 = ty << 3;
    const int cbase = tx << 1;

    ull acc[4][8];
#pragma unroll
    for (int q = 0; q < 4; ++q) {
        ull b0 = splat2(bias[bn + cbase + (q << 5)]);
        ull b1 = splat2(bias[bn + cbase + (q << 5) + 1]);
#pragma unroll
        for (int rp = 0; rp < 4; ++rp) {
            acc[rp][(q << 1)]     = b0;
            acc[rp][(q << 1) + 1] = b1;
        }
    }

    for (int k0 = 0; k0 < IND; k0 += 16) {
#pragma unroll
        for (int r = 0; r < 2; ++r) {
            int i4 = tid + (r << 8);
            int row = i4 >> 2, kq = (i4 & 3) << 2;
            float4 v = *(const float4*)&A[(size_t)(bm + row) * IND + k0 + kq];
            Asm[kq + 0][row] = v.x;
            Asm[kq + 1][row] = v.y;
            Asm[kq + 2][row] = v.z;
            Asm[kq + 3][row] = v.w;
        }
#pragma unroll
        for (int r = 0; r < 2; ++r) {
            int i4 = tid + (r << 8);
            int kr = i4 >> 5, n4 = (i4 & 31) << 2;
            float4 v = *(const float4*)&W[(size_t)(k0 + kr) * 4096 + bn + n4];
            *(ulonglong2*)&Bsm[kr][n4]     = make_ulonglong2(splat2(v.x), splat2(v.y));
            *(ulonglong2*)&Bsm[kr][n4 + 2] = make_ulonglong2(splat2(v.z), splat2(v.w));
        }
        __syncthreads();
#pragma unroll
        for (int k = 0; k < 16; ++k) {
            ull ap[4];
#pragma unroll
            for (int rp = 0; rp < 4; ++rp)
                ap[rp] = *(const ull*)&Asm[k][row0 + (rp << 1)];
            ulonglong2 bq[4];
#pragma unroll
            for (int q = 0; q < 4; ++q)
                bq[q] = *(const ulonglong2*)&Bsm[k][cbase + (q << 5)];
#pragma unroll
            for (int rp = 0; rp < 4; ++rp)
#pragma unroll
                for (int q = 0; q < 4; ++q) {
                    fma2(acc[rp][(q << 1)],     ap[rp], bq[q].x);
                    fma2(acc[rp][(q << 1) + 1], ap[rp], bq[q].y);
                }
        }
        __syncthreads();
    }
#pragma unroll
    for (int rp = 0; rp < 4; ++rp) {
        size_t r0 = (size_t)(bm + row0 + (rp << 1)) * 4096 + bn + cbase;
        size_t r1 = r0 + 4096;
#pragma unroll
        for (int q = 0; q < 4; ++q) {
            float l0, h0, l1, h1;
            unpack2(acc[rp][(q << 1)],     l0, h0);
            unpack2(acc[rp][(q << 1) + 1], l1, h1);
            *(float2*)&g_xp[r0 + (q << 5)] = make_float2(l0, l1);
            *(float2*)&g_xp[r1 + (q << 5)] = make_float2(h0, h1);
        }
    }
}

// ============ phase 2: PERSISTENT kernel, U resident in smem ==============
// 128 blocks x 512 threads, 1 block/SM (192KB smem), grid barrier per step.
// Block owns 8 units x 4 gates = 32 cols; smem col c: unit=c>>2, gate=c&3,
// colg(c) = (c&3)*1024 + blk*8 + (c>>2).
// 8 k-groups (gg) x 2 warps (w2: 16 cols each); lanes = batch.
// smem: Us[1024][32] 128K persistent | hs[2][256*32] 64K (zred aliases hs[0])
#define SMEM_HS0  131072
#define SMEM_HS1  (131072 + 32768)
#define LSTM_SMEM (131072 + 65536)

__global__ void __launch_bounds__(512, 1) lstm_kernel(const float* __restrict__ U,
                                                      float* __restrict__ out) {
    extern __shared__ unsigned char sm[];
    float* Us   = (float*)sm;                    // [1024][32]
    float* hs0  = (float*)(sm + SMEM_HS0);       // [256][32]
    float* hs1  = (float*)(sm + SMEM_HS1);       // [256][32]
    ull*   zred = (ull*)(sm + SMEM_HS0);         // aliases hs0 after last use

    const int tid = threadIdx.x;
    const int blk = blockIdx.x;
    const int b   = tid & 31;
    const int w2  = (tid >> 5) & 1;
    const int gg  = tid >> 6;
    const int cu  = w2 << 4;

    // staging identity: col sc, row sr + 16*it
    const int sc = tid & 31;
    const int sr = tid >> 5;
    const size_t colg = (size_t)((sc & 3) << 10) + (blk << 3) + (sc >> 2);

    // ---- load this block's U slice into smem ONCE ----
    for (int it = 0; it < 64; ++it) {
        int k = sr + (it << 4);
        Us[(k << 5) + sc] = __ldg(&U[((size_t)k << 12) + colg]);
    }

    // reduction thread identity (tid < 256): unit uf, batch bf
    const int uf = tid >> 5;          // 0..7 for tid<256
    const int bf = tid & 31;
    const int ug = (blk << 3) + uf;
    float creg = 0.0f;                // cell state lives in registers

    __syncthreads();

    // ---- stage h chunk 0 of step 0 ----
    {
        const float* hsrc = g_h[0];
#pragma unroll
        for (int it = 0; it < 4; ++it) {
            float4 v = __ldcg((const float4*)&hsrc[(tid + (it << 9)) << 2]);
            *(float4*)&hs0[(tid + (it << 9)) << 2] = v;
        }
    }
    __syncthreads();

    for (int t = 0; t < TT; ++t) {
        const int cur = t & 1;
        const float* hsrc = g_h[cur];

        // xp prefetch for reduction threads (consumed after the GEMM)
        float xpi = 0.f, xpf = 0.f, xpg = 0.f, xpo = 0.f;
        if (tid < 256) {
            const size_t btrow = ((size_t)((bf << 9) | t)) << 12;
            xpi = __ldg(&g_xp[btrow + ug]);
            xpf = __ldg(&g_xp[btrow + 1024 + ug]);
            xpg = __ldg(&g_xp[btrow + 2048 + ug]);
            xpo = __ldg(&g_xp[btrow + 3072 + ug]);
        }

        ull a[8];
#pragma unroll
        for (int q = 0; q < 8; ++q) a[q] = 0ull;

        float4 hr[4];

#pragma unroll 1
        for (int p = 0; p < 4; ++p) {
            // prefetch next h chunk (overlaps compute)
            if (p < 3) {
                const int kb = (p + 1) << 8;
#pragma unroll
                for (int it = 0; it < 4; ++it)
                    hr[it] = __ldcg((const float4*)&hsrc[(kb << 5) + ((tid + (it << 9)) << 2)]);
            }
            // compute this thread's 32-k slice: h LDS.32 + 4 bcast LDS.128 + 8 FFMA2
            {
                const float* up = Us + ((p << 13)) + cu;      // U rows p*256..
                const float* hp = ((p & 1) ? hs1 : hs0) + b;
                const int r0 = gg << 5;
#pragma unroll
                for (int j = 0; j < 32; ++j) {
                    const int roff = (r0 + j) << 5;
                    ull h2 = splat2(hp[roff]);
                    ulonglong2 u0 = *(const ulonglong2*)(up + roff);
                    ulonglong2 u1 = *(const ulonglong2*)(up + roff + 4);
                    ulonglong2 u2 = *(const ulonglong2*)(up + roff + 8);
                    ulonglong2 u3 = *(const ulonglong2*)(up + roff + 12);
                    fma2(a[0], u0.x, h2); fma2(a[1], u0.y, h2);
                    fma2(a[2], u1.x, h2); fma2(a[3], u1.y, h2);
                    fma2(a[4], u2.x, h2); fma2(a[5], u2.y, h2);
                    fma2(a[6], u3.x, h2); fma2(a[7], u3.y, h2);
                }
            }
            // store prefetched chunk into the other buffer
            if (p < 3) {
                float* hd = (p & 1) ? hs0 : hs1;
#pragma unroll
                for (int it = 0; it < 4; ++it)
                    *(float4*)&hd[(tid + (it << 9)) << 2] = hr[it];
            }
            __syncthreads();
        }

        // ---- split-K partials (zred aliases hs0; safe after last sync) ----
#pragma unroll
        for (int q = 0; q < 4; ++q) {
            const int u8 = (w2 << 2) + q;
            *(ulonglong2*)&zred[((((gg << 3) | u8) << 5) | b) << 1] =
                make_ulonglong2(a[(q << 1)], a[(q << 1) + 1]);
        }
        __syncthreads();

        // ---- reduce + pointwise (tid < 256) ----
        if (tid < 256) {
            ull s0 = 0ull, s1 = 0ull;
#pragma unroll
            for (int g8 = 0; g8 < 8; ++g8) {
                ulonglong2 v = *(const ulonglong2*)&zred[((((g8 << 3) | uf) << 5) | bf) << 1];
                add2(s0, v.x);
                add2(s1, v.y);
            }
            float zi, zf, zg, zo;
            unpack2(s0, zi, zf);
            unpack2(s1, zg, zo);
            zi += xpi; zf += xpf; zg += xpg; zo += xpo;

            float ig = 1.0f / (1.0f + __expf(-zi));
            float fg = 1.0f / (1.0f + __expf(-zf));
            float gv = tanhf(zg);
            float og = 1.0f / (1.0f + __expf(-zo));

            creg = fg * creg + ig * gv;
            float h = og * tanhf(creg);

            g_h[cur ^ 1][(ug << 5) + bf] = h;
            out[(((size_t)((bf << 9) | t)) << 10) + ug] = h;
        }

        if (t < TT - 1) {
            // CG-style grid barrier: syncthreads + one-thread release/acquire
            __syncthreads();
            if (tid == 0) {
                asm volatile("red.release.gpu.global.add.u32 [%0], %1;"
                             :: "l"(&g_bar), "r"(1u) : "memory");
                const unsigned target = (unsigned)(t + 1) * NB;
                unsigned v, spins = 0;
                do {
                    asm volatile("ld.acquire.gpu.global.u32 %0, [%1];"
                                 : "=r"(v) : "l"(&g_bar) : "memory");
                } while (v < target && ++spins < 0x40000000u);
            }
            __syncthreads();
            // stage chunk 0 of next step's h (now globally visible) into hs0
            const float* hn = g_h[cur ^ 1];
#pragma unroll
            for (int it = 0; it < 4; ++it) {
                float4 v = __ldcg((const float4*)&hn[(tid + (it << 9)) << 2]);
                *(float4*)&hs0[(tid + (it << 9)) << 2] = v;
            }
            __syncthreads();
        }
    }
}

// ========================= launcher ======================================
extern "C" void kernel_launch(void* const* d_in, const int* in_sizes, int n_in,
                              void* d_out, int out_size) {
    const float* inputs = (const float*)d_in[0];
    const float* W      = (const float*)d_in[1];
    const float* U      = (const float*)d_in[2];
    const float* bias   = (const float*)d_in[3];
    float* out = (float*)d_out;

    cudaFuncSetAttribute(lstm_kernel,
                         cudaFuncAttributeMaxDynamicSharedMemorySize, LSTM_SMEM);

    init_kernel<<<64, 256>>>();
    dim3 g1(32, 128);
    xproj_kernel<<<g1, 256>>>(inputs, W, bias);
    lstm_kernel<<<NB, 512, LSTM_SMEM>>>(U, out);
}

// round 8
// speedup vs baseline: 1.4947x; 1.0605x over previous
#include <cuda_runtime.h>
#include <math.h>

typedef unsigned long long ull;

#define NB 128
#define UNITS 1024
#define BATCH 32
#define TT 512
#define IND 512

// ---------------- static device scratch (allocation-free) ----------------
__device__ float    g_xp[(size_t)BATCH * TT * 4 * UNITS];  // [(b*512+t)][4096]
__device__ float    g_h[2][UNITS * BATCH];                 // [unit][batch], double buffered
__device__ unsigned g_bar;

// ---------------- f32x2 helpers (FFMA2 = 2x fp32 FMA rate on sm_103a) -----
__device__ __forceinline__ void fma2(ull& d, ull a, ull b) {
    asm("fma.rn.f32x2 %0, %1, %2, %0;" : "+l"(d) : "l"(a), "l"(b));
}
__device__ __forceinline__ void add2(ull& d, ull a) {
    asm("add.rn.f32x2 %0, %0, %1;" : "+l"(d) : "l"(a));
}
__device__ __forceinline__ ull splat2(float x) {
    ull r; asm("mov.b64 %0, {%1, %1};" : "=l"(r) : "f"(x)); return r;
}
__device__ __forceinline__ void unpack2(ull v, float& lo, float& hi) {
    asm("mov.b64 {%0, %1}, %2;" : "=f"(lo), "=f"(hi) : "l"(v));
}

// ===================== init: zero h0 + barrier ===========================
__global__ void init_kernel() {
    int i = blockIdx.x * blockDim.x + threadIdx.x;
    if (i == 0) g_bar = 0u;
    for (int j = i; j < UNITS * BATCH; j += gridDim.x * blockDim.x)
        g_h[0][j] = 0.0f;
}

// ============ phase 1: g_xp = inputs @ W + b  (FFMA2 SGEMM) ===============
__global__ __launch_bounds__(256) void xproj_kernel(const float* __restrict__ A,
                                                    const float* __restrict__ W,
                                                    const float* __restrict__ bias) {
    __shared__ float Asm[16][132];
    __shared__ ull   Bsm[16][128];

    const int tid = threadIdx.x;
    const int bn = blockIdx.x << 7;
    const int bm = blockIdx.y << 7;
    const int tx = tid & 15;
    const int ty = tid >> 4;
    const int row0 = ty << 3;
    const int cbase = tx << 1;

    ull acc[4][8];
#pragma unroll
    for (int q = 0; q < 4; ++q) {
        ull b0 = splat2(bias[bn + cbase + (q << 5)]);
        ull b1 = splat2(bias[bn + cbase + (q << 5) + 1]);
#pragma unroll
        for (int rp = 0; rp < 4; ++rp) {
            acc[rp][(q << 1)]     = b0;
            acc[rp][(q << 1) + 1] = b1;
        }
    }

    for (int k0 = 0; k0 < IND; k0 += 16) {
#pragma unroll
        for (int r = 0; r < 2; ++r) {
            int i4 = tid + (r << 8);
            int row = i4 >> 2, kq = (i4 & 3) << 2;
            float4 v = *(const float4*)&A[(size_t)(bm + row) * IND + k0 + kq];
            Asm[kq + 0][row] = v.x;
            Asm[kq + 1][row] = v.y;
            Asm[kq + 2][row] = v.z;
            Asm[kq + 3][row] = v.w;
        }
#pragma unroll
        for (int r = 0; r < 2; ++r) {
            int i4 = tid + (r << 8);
            int kr = i4 >> 5, n4 = (i4 & 31) << 2;
            float4 v = *(const float4*)&W[(size_t)(k0 + kr) * 4096 + bn + n4];
            *(ulonglong2*)&Bsm[kr][n4]     = make_ulonglong2(splat2(v.x), splat2(v.y));
            *(ulonglong2*)&Bsm[kr][n4 + 2] = make_ulonglong2(splat2(v.z), splat2(v.w));
        }
        __syncthreads();
#pragma unroll
        for (int k = 0; k < 16; ++k) {
            ull ap[4];
#pragma unroll
            for (int rp = 0; rp < 4; ++rp)
                ap[rp] = *(const ull*)&Asm[k][row0 + (rp << 1)];
            ulonglong2 bq[4];
#pragma unroll
            for (int q = 0; q < 4; ++q)
                bq[q] = *(const ulonglong2*)&Bsm[k][cbase + (q << 5)];
#pragma unroll
            for (int rp = 0; rp < 4; ++rp)
#pragma unroll
                for (int q = 0; q < 4; ++q) {
                    fma2(acc[rp][(q << 1)],     ap[rp], bq[q].x);
                    fma2(acc[rp][(q << 1) + 1], ap[rp], bq[q].y);
                }
        }
        __syncthreads();
    }
#pragma unroll
    for (int rp = 0; rp < 4; ++rp) {
        size_t r0 = (size_t)(bm + row0 + (rp << 1)) * 4096 + bn + cbase;
        size_t r1 = r0 + 4096;
#pragma unroll
        for (int q = 0; q < 4; ++q) {
            float l0, h0, l1, h1;
            unpack2(acc[rp][(q << 1)],     l0, h0);
            unpack2(acc[rp][(q << 1) + 1], l1, h1);
            *(float2*)&g_xp[r0 + (q << 5)] = make_float2(l0, l1);
            *(float2*)&g_xp[r1 + (q << 5)] = make_float2(h0, h1);
        }
    }
}

// ============ phase 2: PERSISTENT kernel, register-tiled ==================
// 128 blocks x 512 threads, 1 block/SM (192KB smem), grid barrier per step.
// Block owns 32 gate-cols: col c -> unit=c>>2, gate=c&3,
//   colg(c) = (c&3)*1024 + blk*8 + (c>>2).
// 16 warps = 16-way split-K (64 k each). Lane (cg=ln>>3, bg=ln&7) owns an
// 8-col x 4-batch register tile (16 ull acc). Per k: 2 LDS.128 (U) +
// 1 LDG.128 (h, direct from L2, pipelined depth 4) + 4 MOV + 16 FFMA2.
// smem: Us[1024][32] 128K persistent | zred ull[16][32][16] 64K
#define ZRED_OFF  131072
#define LSTM_SMEM (131072 + 65536)

__global__ void __launch_bounds__(512, 1) lstm_kernel(const float* __restrict__ U,
                                                      float* __restrict__ out) {
    extern __shared__ unsigned char sm[];
    float* Us   = (float*)sm;                    // [1024][32]
    ull*   zred = (ull*)(sm + ZRED_OFF);         // [w][b][cp]

    const int tid = threadIdx.x;
    const int blk = blockIdx.x;
    const int w   = tid >> 5;        // k-slice 0..15
    const int ln  = tid & 31;
    const int cg  = ln >> 3;         // col-group 0..3 (cols 8cg..8cg+7)
    const int bg  = ln & 7;          // batch-group 0..7 (b 4bg..4bg+3)
    const int k0  = w << 6;
    const int hoff = bg << 2;
    const int uoff = cg << 3;

    // ---- load this block's U slice into smem ONCE ----
    {
        const int sc = tid & 31;
        const int sr = tid >> 5;
        const size_t colg = (size_t)((sc & 3) << 10) + (blk << 3) + (sc >> 2);
        for (int it = 0; it < 64; ++it) {
            int k = sr + (it << 4);
            Us[(k << 5) + sc] = __ldg(&U[((size_t)k << 12) + colg]);
        }
    }

    // reduction thread identity (tid < 256): unit uf, batch bf
    const int uf = tid >> 5;
    const int bf = tid & 31;
    const int ug = (blk << 3) + uf;
    float creg = 0.0f;               // cell state in registers

    __syncthreads();

    for (int t = 0; t < TT; ++t) {
        const int cur = t & 1;
        const float* hsrc = g_h[cur];

        // xp prefetch (reduction threads; overlaps the GEMM)
        float xpi = 0.f, xpf = 0.f, xpg = 0.f, xpo = 0.f;
        if (tid < 256) {
            const size_t btrow = ((size_t)((bf << 9) | t)) << 12;
            xpi = __ldg(&g_xp[btrow + ug]);
            xpf = __ldg(&g_xp[btrow + 1024 + ug]);
            xpg = __ldg(&g_xp[btrow + 2048 + ug]);
            xpo = __ldg(&g_xp[btrow + 3072 + ug]);
        }

        // ---- k-loop: 64 k per warp, no syncs, h from L2 pipelined ----
        ull acc[16];
#pragma unroll
        for (int q = 0; q < 16; ++q) acc[q] = 0ull;

        float4 hq[4];
#pragma unroll
        for (int i = 0; i < 4; ++i)
            hq[i] = __ldcg((const float4*)&hsrc[((k0 + i) << 5) + hoff]);

#pragma unroll 8
        for (int k = 0; k < 64; ++k) {
            float4 hv = hq[k & 3];
            if (k < 60)
                hq[k & 3] = __ldcg((const float4*)&hsrc[((k0 + k + 4) << 5) + hoff]);
            const float* up = &Us[((k0 + k) << 5) + uoff];
            ulonglong2 u01 = *(const ulonglong2*)up;
            ulonglong2 u23 = *(const ulonglong2*)(up + 4);
            ull h0 = splat2(hv.x), h1 = splat2(hv.y);
            ull h2 = splat2(hv.z), h3 = splat2(hv.w);
            fma2(acc[0],  u01.x, h0); fma2(acc[1],  u01.y, h0);
            fma2(acc[2],  u23.x, h0); fma2(acc[3],  u23.y, h0);
            fma2(acc[4],  u01.x, h1); fma2(acc[5],  u01.y, h1);
            fma2(acc[6],  u23.x, h1); fma2(acc[7],  u23.y, h1);
            fma2(acc[8],  u01.x, h2); fma2(acc[9],  u01.y, h2);
            fma2(acc[10], u23.x, h2); fma2(acc[11], u23.y, h2);
            fma2(acc[12], u01.x, h3); fma2(acc[13], u01.y, h3);
            fma2(acc[14], u23.x, h3); fma2(acc[15], u23.y, h3);
        }

        // ---- write split-K partials: zred[w][b=4bg+bq][cp=4cg+i] ----
        {
            ull* zr = zred + (w << 9) + (bg << 6) + (cg << 2);
#pragma unroll
            for (int bq = 0; bq < 4; ++bq) {
                *(ulonglong2*)(zr + (bq << 4))     = make_ulonglong2(acc[bq * 4 + 0], acc[bq * 4 + 1]);
                *(ulonglong2*)(zr + (bq << 4) + 2) = make_ulonglong2(acc[bq * 4 + 2], acc[bq * 4 + 3]);
            }
        }
        __syncthreads();

        // ---- reduce + pointwise (tid < 256) ----
        if (tid < 256) {
            ull s0 = 0ull, s1 = 0ull;
            const ull* zp = zred + (bf << 4) + (uf << 1);
#pragma unroll
            for (int wi = 0; wi < 16; ++wi) {
                ulonglong2 v = *(const ulonglong2*)(zp + (wi << 9));
                add2(s0, v.x);
                add2(s1, v.y);
            }
            float zi, zf, zg, zo;
            unpack2(s0, zi, zf);
            unpack2(s1, zg, zo);
            zi += xpi; zf += xpf; zg += xpg; zo += xpo;

            float ig = 1.0f / (1.0f + __expf(-zi));
            float fg = 1.0f / (1.0f + __expf(-zf));
            float gv = 1.0f - 2.0f / (1.0f + __expf(2.0f * zg));
            float og = 1.0f / (1.0f + __expf(-zo));

            creg = fg * creg + ig * gv;
            float th = 1.0f - 2.0f / (1.0f + __expf(2.0f * creg));
            float h = og * th;

            g_h[cur ^ 1][(ug << 5) + bf] = h;
            out[(((size_t)((bf << 9) | t)) << 10) + ug] = h;
        }

        if (t < TT - 1) {
            // grid barrier: syncthreads + one-thread release/acquire spin
            __syncthreads();
            if (tid == 0) {
                asm volatile("red.release.gpu.global.add.u32 [%0], %1;"
                             :: "l"(&g_bar), "r"(1u) : "memory");
                const unsigned target = (unsigned)(t + 1) * NB;
                unsigned v, spins = 0;
                do {
                    asm volatile("ld.acquire.gpu.global.u32 %0, [%1];"
                                 : "=r"(v) : "l"(&g_bar) : "memory");
                } while (v < target && ++spins < 0x40000000u);
            }
            __syncthreads();
        }
    }
}

// ========================= launcher ======================================
extern "C" void kernel_launch(void* const* d_in, const int* in_sizes, int n_in,
                              void* d_out, int out_size) {
    const float* inputs = (const float*)d_in[0];
    const float* W      = (const float*)d_in[1];
    const float* U      = (const float*)d_in[2];
    const float* bias   = (const float*)d_in[3];
    float* out = (float*)d_out;

    cudaFuncSetAttribute(lstm_kernel,
                         cudaFuncAttributeMaxDynamicSharedMemorySize, LSTM_SMEM);

    init_kernel<<<64, 256>>>();
    dim3 g1(32, 128);
    xproj_kernel<<<g1, 256>>>(inputs, W, bias);
    lstm_kernel<<<NB, 512, LSTM_SMEM>>>(U, out);
}

// round 10
// speedup vs baseline: 2.0656x; 1.3819x over previous
#include <cuda_runtime.h>
#include <math.h>

typedef unsigned long long ull;

#define NB 128
#define UNITS 1024
#define BATCH 32
#define TT 512
#define IND 512

// ---------------- static device scratch (allocation-free) ----------------
// g_xp layout (transposed): [(t*32 + b)][4096]  -> per-step contiguous slab
__device__ float    g_xp[(size_t)BATCH * TT * 4 * UNITS];
__device__ float    g_h[2][UNITS * BATCH];      // [unit][batch], double buffered
__device__ unsigned g_bar;

// ---------------- f32x2 helpers (FFMA2) -----------------------------------
__device__ __forceinline__ void fma2(ull& d, ull a, ull b) {
    asm("fma.rn.f32x2 %0, %1, %2, %0;" : "+l"(d) : "l"(a), "l"(b));
}
__device__ __forceinline__ void add2(ull& d, ull a) {
    asm("add.rn.f32x2 %0, %0, %1;" : "+l"(d) : "l"(a));
}
__device__ __forceinline__ ull splat2(float x) {
    ull r; asm("mov.b64 %0, {%1, %1};" : "=l"(r) : "f"(x)); return r;
}
__device__ __forceinline__ void unpack2(ull v, float& lo, float& hi) {
    asm("mov.b64 {%0, %1}, %2;" : "=f"(lo), "=f"(hi) : "l"(v));
}

// ===================== init: zero h0 + barrier ===========================
__global__ void init_kernel() {
    int i = blockIdx.x * blockDim.x + threadIdx.x;
    if (i == 0) g_bar = 0u;
    for (int j = i; j < UNITS * BATCH; j += gridDim.x * blockDim.x)
        g_h[0][j] = 0.0f;
}

// ============ phase 1: g_xp = inputs @ W + b  (FFMA2 SGEMM) ===============
__global__ __launch_bounds__(256) void xproj_kernel(const float* __restrict__ A,
                                                    const float* __restrict__ W,
                                                    const float* __restrict__ bias) {
    __shared__ float Asm[16][132];
    __shared__ ull   Bsm[16][128];

    const int tid = threadIdx.x;
    const int bn = blockIdx.x << 7;
    const int bm = blockIdx.y << 7;
    const int tx = tid & 15;
    const int ty = tid >> 4;
    const int row0 = ty << 3;
    const int cbase = tx << 1;

    ull acc[4][8];
#pragma unroll
    for (int q = 0; q < 4; ++q) {
        ull b0 = splat2(bias[bn + cbase + (q << 5)]);
        ull b1 = splat2(bias[bn + cbase + (q << 5) + 1]);
#pragma unroll
        for (int rp = 0; rp < 4; ++rp) {
            acc[rp][(q << 1)]     = b0;
            acc[rp][(q << 1) + 1] = b1;
        }
    }

    for (int k0 = 0; k0 < IND; k0 += 16) {
#pragma unroll
        for (int r = 0; r < 2; ++r) {
            int i4 = tid + (r << 8);
            int row = i4 >> 2, kq = (i4 & 3) << 2;
            float4 v = *(const float4*)&A[(size_t)(bm + row) * IND + k0 + kq];
            Asm[kq + 0][row] = v.x;
            Asm[kq + 1][row] = v.y;
            Asm[kq + 2][row] = v.z;
            Asm[kq + 3][row] = v.w;
        }
#pragma unroll
        for (int r = 0; r < 2; ++r) {
            int i4 = tid + (r << 8);
            int kr = i4 >> 5, n4 = (i4 & 31) << 2;
            float4 v = *(const float4*)&W[(size_t)(k0 + kr) * 4096 + bn + n4];
            *(ulonglong2*)&Bsm[kr][n4]     = make_ulonglong2(splat2(v.x), splat2(v.y));
            *(ulonglong2*)&Bsm[kr][n4 + 2] = make_ulonglong2(splat2(v.z), splat2(v.w));
        }
        __syncthreads();
#pragma unroll
        for (int k = 0; k < 16; ++k) {
            ull ap[4];
#pragma unroll
            for (int rp = 0; rp < 4; ++rp)
                ap[rp] = *(const ull*)&Asm[k][row0 + (rp << 1)];
            ulonglong2 bq[4];
#pragma unroll
            for (int q = 0; q < 4; ++q)
                bq[q] = *(const ulonglong2*)&Bsm[k][cbase + (q << 5)];
#pragma unroll
            for (int rp = 0; rp < 4; ++rp)
#pragma unroll
                for (int q = 0; q < 4; ++q) {
                    fma2(acc[rp][(q << 1)],     ap[rp], bq[q].x);
                    fma2(acc[rp][(q << 1) + 1], ap[rp], bq[q].y);
                }
        }
        __syncthreads();
    }
    // epilogue with [t][b] transpose: global row gr -> new row (gr&511)*32 + (gr>>9)
#pragma unroll
    for (int rp = 0; rp < 4; ++rp) {
        const int gr = bm + row0 + (rp << 1);
        size_t nr0 = (size_t)(((gr & 511) << 5) + (gr >> 9)) * 4096 + bn + cbase;
        size_t nr1 = nr0 + (32u << 12);     // gr+1: t+1 -> +32 rows
#pragma unroll
        for (int q = 0; q < 4; ++q) {
            float l0, h0, l1, h1;
            unpack2(acc[rp][(q << 1)],     l0, h0);
            unpack2(acc[rp][(q << 1) + 1], l1, h1);
            *(float2*)&g_xp[nr0 + (q << 5)] = make_float2(l0, l1);
            *(float2*)&g_xp[nr1 + (q << 5)] = make_float2(h0, h1);
        }
    }
}

// ============ phase 2: PERSISTENT kernel, register-tiled ==================
// 128 blocks x 512 threads, 1 block/SM (192KB smem), grid barrier per step.
// Block owns 32 gate-cols: col c -> unit=c>>2, gate=c&3,
//   colg(c) = (c&3)*1024 + blk*8 + (c>>2).
// 16 warps = 16-way split-K (64 k each). Lane (cg=ln>>3, bg=ln&7) owns an
// 8-col x 4-batch register tile (16 ull acc). Per k: 2 LDS.128 (U) +
// 1 LDG.128 (h from L2, pipelined depth 4) + 4 MOV + 16 FFMA2.
// Exchange: each acc ulonglong2 = ALL 4 GATES of unit 2cg+h, b=4bg+bq.
//   zq[(w*8 + bq*2 + h)*32 + ln]  (ulonglong2) -> STS/LDS both conflict-free.
// Reducer tid<256: jr=tid>>5, ln=tid&31 -> unit=2*(ln>>3)+(jr&1),
//   b=4*(ln&7)+(jr>>1); sums zq[(w*8+jr)*32+ln] over w.
// smem: Us[1024][32] 128K persistent | zq ulonglong2[16*8*32] 64K
#define ZRED_OFF  131072
#define LSTM_SMEM (131072 + 65536)

__global__ void __launch_bounds__(512, 1) lstm_kernel(const float* __restrict__ U,
                                                      float* __restrict__ out) {
    extern __shared__ unsigned char sm[];
    float*      Us = (float*)sm;                       // [1024][32]
    ulonglong2* zq = (ulonglong2*)(sm + ZRED_OFF);     // [w*8+j][32]

    const int tid = threadIdx.x;
    const int blk = blockIdx.x;
    const int w   = tid >> 5;
    const int ln  = tid & 31;
    const int cg  = ln >> 3;
    const int bg  = ln & 7;
    const int k0  = w << 6;
    const int hoff = bg << 2;
    const int uoff = cg << 3;

    // ---- load this block's U slice into smem ONCE ----
    {
        const int sc = tid & 31;
        const int sr = tid >> 5;
        const size_t colg = (size_t)((sc & 3) << 10) + (blk << 3) + (sc >> 2);
        for (int it = 0; it < 64; ++it) {
            int k = sr + (it << 4);
            Us[(k << 5) + sc] = __ldg(&U[((size_t)k << 12) + colg]);
        }
    }

    // reducer identity (tid < 256)
    const int jr = tid >> 5;                 // 0..7 for tid<256
    const int uf = ((ln >> 3) << 1) + (jr & 1);
    const int bf = ((ln & 7) << 2) + (jr >> 1);
    const int ug = (blk << 3) + uf;
    float creg = 0.0f;                       // cell state in registers

    __syncthreads();

    for (int t = 0; t < TT; ++t) {
        const int cur = t & 1;
        const float* hsrc = g_h[cur];

        // xp prefetch (reducers; consumed after the GEMM). Transposed layout.
        float xpi = 0.f, xpf = 0.f, xpg = 0.f, xpo = 0.f;
        if (tid < 256) {
            const size_t btrow = ((size_t)((t << 5) + bf)) << 12;
            xpi = __ldg(&g_xp[btrow + ug]);
            xpf = __ldg(&g_xp[btrow + 1024 + ug]);
            xpg = __ldg(&g_xp[btrow + 2048 + ug]);
            xpo = __ldg(&g_xp[btrow + 3072 + ug]);
        }

        // ---- k-loop: 64 k per warp, no syncs, h from L2 pipelined ----
        ull acc[16];
#pragma unroll
        for (int q = 0; q < 16; ++q) acc[q] = 0ull;

        float4 hq[4];
#pragma unroll
        for (int i = 0; i < 4; ++i)
            hq[i] = __ldcg((const float4*)&hsrc[((k0 + i) << 5) + hoff]);

#pragma unroll 8
        for (int k = 0; k < 64; ++k) {
            float4 hv = hq[k & 3];
            if (k < 60)
                hq[k & 3] = __ldcg((const float4*)&hsrc[((k0 + k + 4) << 5) + hoff]);
            const float* up = &Us[((k0 + k) << 5) + uoff];
            ulonglong2 u01 = *(const ulonglong2*)up;
            ulonglong2 u23 = *(const ulonglong2*)(up + 4);
            ull h0 = splat2(hv.x), h1 = splat2(hv.y);
            ull h2 = splat2(hv.z), h3 = splat2(hv.w);
            fma2(acc[0],  u01.x, h0); fma2(acc[1],  u01.y, h0);
            fma2(acc[2],  u23.x, h0); fma2(acc[3],  u23.y, h0);
            fma2(acc[4],  u01.x, h1); fma2(acc[5],  u01.y, h1);
            fma2(acc[6],  u23.x, h1); fma2(acc[7],  u23.y, h1);
            fma2(acc[8],  u01.x, h2); fma2(acc[9],  u01.y, h2);
            fma2(acc[10], u23.x, h2); fma2(acc[11], u23.y, h2);
            fma2(acc[12], u01.x, h3); fma2(acc[13], u01.y, h3);
            fma2(acc[14], u23.x, h3); fma2(acc[15], u23.y, h3);
        }

        // ---- write split-K partials: conflict-free STS.128 ----
        // acc[bq*4+2h], acc[bq*4+2h+1] = (i,f | g,o) of unit 2cg+h, b=4bg+bq
        {
            ulonglong2* zw = zq + (w << 3) * 32 + ln;
#pragma unroll
            for (int bq = 0; bq < 4; ++bq) {
                zw[((bq << 1) + 0) << 5] = make_ulonglong2(acc[(bq << 2) + 0], acc[(bq << 2) + 1]);
                zw[((bq << 1) + 1) << 5] = make_ulonglong2(acc[(bq << 2) + 2], acc[(bq << 2) + 3]);
            }
        }
        __syncthreads();

        // ---- reduce + pointwise (tid < 256), conflict-free LDS.128 ----
        if (tid < 256) {
            ull s0 = 0ull, s1 = 0ull;
            const ulonglong2* zp = zq + (jr << 5) + ln;
#pragma unroll
            for (int wi = 0; wi < 16; ++wi) {
                ulonglong2 v = zp[wi << 8];
                add2(s0, v.x);
                add2(s1, v.y);
            }
            float zi, zf, zg, zo;
            unpack2(s0, zi, zf);
            unpack2(s1, zg, zo);
            zi += xpi; zf += xpf; zg += xpg; zo += xpo;

            float ig = 1.0f / (1.0f + __expf(-zi));
            float fg = 1.0f / (1.0f + __expf(-zf));
            float gv = 1.0f - 2.0f / (1.0f + __expf(2.0f * zg));
            float og = 1.0f / (1.0f + __expf(-zo));

            creg = fg * creg + ig * gv;
            float th = 1.0f - 2.0f / (1.0f + __expf(2.0f * creg));
            float h = og * th;

            g_h[cur ^ 1][(ug << 5) + bf] = h;
            out[(((size_t)((bf << 9) | t)) << 10) + ug] = h;
        }

        if (t < TT - 1) {
            // grid barrier: syncthreads + one-thread release/acquire spin
            __syncthreads();
            if (tid == 0) {
                asm volatile("red.release.gpu.global.add.u32 [%0], %1;"
                             :: "l"(&g_bar), "r"(1u) : "memory");
                const unsigned target = (unsigned)(t + 1) * NB;
                unsigned v, spins = 0;
                do {
                    asm volatile("ld.acquire.gpu.global.u32 %0, [%1];"
                                 : "=r"(v) : "l"(&g_bar) : "memory");
                } while (v < target && ++spins < 0x40000000u);
            }
            __syncthreads();
        }
    }
}

// ========================= launcher ======================================
extern "C" void kernel_launch(void* const* d_in, const int* in_sizes, int n_in,
                              void* d_out, int out_size) {
    const float* inputs = (const float*)d_in[0];
    const float* W      = (const float*)d_in[1];
    const float* U      = (const float*)d_in[2];
    const float* bias   = (const float*)d_in[3];
    float* out = (float*)d_out;

    cudaFuncSetAttribute(lstm_kernel,
                         cudaFuncAttributeMaxDynamicSharedMemorySize, LSTM_SMEM);

    init_kernel<<<64, 256>>>();
    dim3 g1(32, 128);
    xproj_kernel<<<g1, 256>>>(inputs, W, bias);
    lstm_kernel<<<NB, 512, LSTM_SMEM>>>(U, out);
}

// round 15
// speedup vs baseline: 2.4002x; 1.1620x over previous
#include <cuda_runtime.h>
#include <cuda_bf16.h>
#include <math.h>

typedef unsigned long long ull;
typedef unsigned int u32;

#define NB 128
#define UNITS 1024
#define BATCH 32
#define TT 512
#define IND 512

// ---------------- static device scratch (allocation-free) ----------------
// g_xp layout (transposed): [(t*32 + b)][4096]  -> per-step contiguous slab
__device__ float    g_xp[(size_t)BATCH * TT * 4 * UNITS];
__device__ float    g_h[2][UNITS * BATCH];      // [unit][batch], double buffered
__device__ unsigned g_bar;
// bf16 hi/lo splits for the tensor-core xproj GEMM
__device__ __nv_bfloat16 g_Ah[(size_t)16384 * 512];
__device__ __nv_bfloat16 g_Al[(size_t)16384 * 512];
__device__ __nv_bfloat16 g_Wh[(size_t)512 * 4096];
__device__ __nv_bfloat16 g_Wl[(size_t)512 * 4096];

// ---------------- f32x2 helpers (FFMA2) -----------------------------------
__device__ __forceinline__ void fma2(ull& d, ull a, ull b) {
    asm("fma.rn.f32x2 %0, %1, %2, %0;" : "+l"(d) : "l"(a), "l"(b));
}
__device__ __forceinline__ void add2(ull& d, ull a) {
    asm("add.rn.f32x2 %0, %0, %1;" : "+l"(d) : "l"(a));
}
__device__ __forceinline__ ull splat2(float x) {
    ull r; asm("mov.b64 %0, {%1, %1};" : "=l"(r) : "f"(x)); return r;
}
__device__ __forceinline__ void unpack2(ull v, float& lo, float& hi) {
    asm("mov.b64 {%0, %1}, %2;" : "=f"(lo), "=f"(hi) : "l"(v));
}

// ---------------- mma helpers ---------------------------------------------
__device__ __forceinline__ u32 smem_u32(const void* p) {
    return (u32)__cvta_generic_to_shared(p);
}
__device__ __forceinline__ void ldsm4(u32* r, u32 addr) {
    asm volatile("ldmatrix.sync.aligned.m8n8.x4.shared.b16 {%0,%1,%2,%3}, [%4];"
                 : "=r"(r[0]), "=r"(r[1]), "=r"(r[2]), "=r"(r[3]) : "r"(addr));
}
__device__ __forceinline__ void ldsm4t(u32* r, u32 addr) {
    asm volatile("ldmatrix.sync.aligned.m8n8.x4.trans.shared.b16 {%0,%1,%2,%3}, [%4];"
                 : "=r"(r[0]), "=r"(r[1]), "=r"(r[2]), "=r"(r[3]) : "r"(addr));
}
__device__ __forceinline__ void mma16816(float* cc, const u32* aa, u32 b0, u32 b1) {
    asm volatile(
        "mma.sync.aligned.m16n8k16.row.col.f32.bf16.bf16.f32 "
        "{%0,%1,%2,%3}, {%4,%5,%6,%7}, {%8,%9}, {%0,%1,%2,%3};"
        : "+f"(cc[0]), "+f"(cc[1]), "+f"(cc[2]), "+f"(cc[3])
        : "r"(aa[0]), "r"(aa[1]), "r"(aa[2]), "r"(aa[3]), "r"(b0), "r"(b1));
}

// ===================== init: zero h0 + barrier ===========================
__global__ void init_kernel() {
    int i = blockIdx.x * blockDim.x + threadIdx.x;
    if (i == 0) g_bar = 0u;
    for (int j = i; j < UNITS * BATCH; j += gridDim.x * blockDim.x)
        g_h[0][j] = 0.0f;
}

// ===================== split: fp32 -> bf16 hi/lo =========================
__global__ void split_kernel(const float* __restrict__ A, const float* __restrict__ W) {
    int i = blockIdx.x * blockDim.x + threadIdx.x;
    int n = gridDim.x * blockDim.x;
    for (size_t j = i; j < (size_t)16384 * 512; j += n) {
        float v = A[j];
        __nv_bfloat16 hv = __float2bfloat16(v);
        g_Ah[j] = hv;
        g_Al[j] = __float2bfloat16(v - __bfloat162float(hv));
    }
    for (size_t j = i; j < (size_t)512 * 4096; j += n) {
        float v = W[j];
        __nv_bfloat16 hv = __float2bfloat16(v);
        g_Wh[j] = hv;
        g_Wl[j] = __float2bfloat16(v - __bfloat162float(hv));
    }
}

// ============ phase 1: tensor-core xproj (bf16 split, 3-MMA) ==============
// C[16384x4096] = A[16384x512] @ W[512x4096] + b, written transposed to g_xp.
// Block tile 128x128, 256 thr (8 warps: 2m x 4n), warp tile 64x32.
#define PA 24    // As pitch in bf16 (48B; ldmatrix conflict-free)
#define PB 136   // Bs pitch in bf16 (272B; ldmatrix.trans conflict-free)

__global__ __launch_bounds__(256) void xproj_mma(const float* __restrict__ bias) {
    __shared__ __nv_bfloat16 Ash[128 * PA];
    __shared__ __nv_bfloat16 Asl[128 * PA];
    __shared__ __nv_bfloat16 Bsh[16 * PB];
    __shared__ __nv_bfloat16 Bsl[16 * PB];

    const int tid = threadIdx.x;
    const int wid = tid >> 5;
    const int ln  = tid & 31;
    const int bm  = blockIdx.y << 7;
    const int bn  = blockIdx.x << 7;
    const int wm  = wid >> 2;
    const int wn  = wid & 3;

    float cfrag[4][4][4];
#pragma unroll
    for (int mi = 0; mi < 4; ++mi)
#pragma unroll
        for (int nj = 0; nj < 4; ++nj)
#pragma unroll
            for (int q = 0; q < 4; ++q) cfrag[mi][nj][q] = 0.0f;

    // staging identities
    const int ar = tid >> 1;
    const int ac = (tid & 1) << 3;
    const int br = tid >> 4;
    const int bc = (tid & 15) << 3;
    const __nv_bfloat16* gAh = g_Ah + (size_t)(bm + ar) * 512 + ac;
    const __nv_bfloat16* gAl = g_Al + (size_t)(bm + ar) * 512 + ac;
    const __nv_bfloat16* gBh = g_Wh + (size_t)br * 4096 + bn + bc;
    const __nv_bfloat16* gBl = g_Wl + (size_t)br * 4096 + bn + bc;

    uint4 pah = *(const uint4*)gAh;
    uint4 pal = *(const uint4*)gAl;
    uint4 pbh = *(const uint4*)gBh;
    uint4 pbl = *(const uint4*)gBl;

    // ldmatrix per-thread source coordinates
    const int a_row  = ln & 15;
    const int a_col  = (ln >> 4) << 3;
    const int b_row  = (ln & 7) + (ln & 8);
    const int b_coln = (ln >> 4) << 3;

    for (int s = 0; s < 32; ++s) {
        *(uint4*)&Ash[ar * PA + ac] = pah;
        *(uint4*)&Asl[ar * PA + ac] = pal;
        *(uint4*)&Bsh[br * PB + bc] = pbh;
        *(uint4*)&Bsl[br * PB + bc] = pbl;
        __syncthreads();

        if (s < 31) {
            const int kk = (s + 1) << 4;
            pah = *(const uint4*)(gAh + kk);
            pal = *(const uint4*)(gAl + kk);
            pbh = *(const uint4*)(gBh + (size_t)kk * 4096);
            pbl = *(const uint4*)(gBl + (size_t)kk * 4096);
        }

        u32 ah[4][4];
        u32 al[4][4];
#pragma unroll
        for (int mi = 0; mi < 4; ++mi) {
            const int abase = ((wm << 6) + (mi << 4) + a_row) * PA + a_col;
            ldsm4(ah[mi], smem_u32(&Ash[abase]));
            ldsm4(al[mi], smem_u32(&Asl[abase]));
        }
        u32 bh[2][4];
        u32 bl[2][4];
#pragma unroll
        for (int bj = 0; bj < 2; ++bj) {
            const int bbase = b_row * PB + (wn << 5) + (bj << 4) + b_coln;
            ldsm4t(bh[bj], smem_u32(&Bsh[bbase]));
            ldsm4t(bl[bj], smem_u32(&Bsl[bbase]));
        }

        // 48 MMAs: hi*hi + hi*lo + lo*hi
#pragma unroll
        for (int mi = 0; mi < 4; ++mi) {
#pragma unroll
            for (int nj = 0; nj < 4; ++nj) {
                const int bj = nj >> 1;
                const int rr = (nj & 1) << 1;
                mma16816(cfrag[mi][nj], ah[mi], bh[bj][rr], bh[bj][rr + 1]);
                mma16816(cfrag[mi][nj], ah[mi], bl[bj][rr], bl[bj][rr + 1]);
                mma16816(cfrag[mi][nj], al[mi], bh[bj][rr], bh[bj][rr + 1]);
            }
        }
        __syncthreads();
    }

    // epilogue: + bias, transposed store (row gr=b*512+t -> (t<<5)+b)
#pragma unroll
    for (int mi = 0; mi < 4; ++mi) {
#pragma unroll
        for (int nj = 0; nj < 4; ++nj) {
            const int row = bm + (wm << 6) + (mi << 4) + (ln >> 2);
            const int col = bn + (wn << 5) + (nj << 3) + ((ln & 3) << 1);
            const float bv0 = __ldg(&bias[col]);
            const float bv1 = __ldg(&bias[col + 1]);
            const size_t nr = (size_t)(((row & 511) << 5) + (row >> 9)) * 4096 + col;
            *(float2*)&g_xp[nr] =
                make_float2(cfrag[mi][nj][0] + bv0, cfrag[mi][nj][1] + bv1);
            // row+8 => t+8 => +8*32 rows => +256*4096 floats
            *(float2*)&g_xp[nr + (size_t)256 * 4096] =
                make_float2(cfrag[mi][nj][2] + bv0, cfrag[mi][nj][3] + bv1);
        }
    }
}

// ============ phase 2: PERSISTENT kernel, register-tiled ==================
// (identical logic to the 5689us round-10 kernel)
#define ZRED_OFF  131072
#define LSTM_SMEM (131072 + 65536)

__global__ void __launch_bounds__(512, 1) lstm_kernel(const float* __restrict__ U,
                                                      float* __restrict__ outp) {
    extern __shared__ unsigned char sm[];
    float*      Us = (float*)sm;                       // [1024][32]
    ulonglong2* zq = (ulonglong2*)(sm + ZRED_OFF);     // [w*8+j][32]

    const int tid = threadIdx.x;
    const int blk = blockIdx.x;
    const int w   = tid >> 5;
    const int ln  = tid & 31;
    const int cg  = ln >> 3;
    const int bg  = ln & 7;
    const int k0  = w << 6;
    const int hoff = bg << 2;
    const int uoff = cg << 3;

    {
        const int sc = tid & 31;
        const int sr = tid >> 5;
        const size_t colg = (size_t)((sc & 3) << 10) + (blk << 3) + (sc >> 2);
        for (int it = 0; it < 64; ++it) {
            int k = sr + (it << 4);
            Us[(k << 5) + sc] = __ldg(&U[((size_t)k << 12) + colg]);
        }
    }

    const int jr = tid >> 5;
    const int uf = ((ln >> 3) << 1) + (jr & 1);
    const int bf = ((ln & 7) << 2) + (jr >> 1);
    const int ug = (blk << 3) + uf;
    float creg = 0.0f;

    __syncthreads();

    for (int t = 0; t < TT; ++t) {
        const int cur = t & 1;
        const float* hsrc = g_h[cur];

        float xpi = 0.f, xpf = 0.f, xpg = 0.f, xpo = 0.f;
        if (tid < 256) {
            const size_t btrow = ((size_t)((t << 5) + bf)) << 12;
            xpi = __ldg(&g_xp[btrow + ug]);
            xpf = __ldg(&g_xp[btrow + 1024 + ug]);
            xpg = __ldg(&g_xp[btrow + 2048 + ug]);
            xpo = __ldg(&g_xp[btrow + 3072 + ug]);
        }

        ull acc[16];
#pragma unroll
        for (int q = 0; q < 16; ++q) acc[q] = 0ull;

        float4 hq[4];
#pragma unroll
        for (int i = 0; i < 4; ++i)
            hq[i] = __ldcg((const float4*)&hsrc[((k0 + i) << 5) + hoff]);

#pragma unroll 8
        for (int k = 0; k < 64; ++k) {
            float4 hv = hq[k & 3];
            if (k < 60)
                hq[k & 3] = __ldcg((const float4*)&hsrc[((k0 + k + 4) << 5) + hoff]);
            const float* up = &Us[((k0 + k) << 5) + uoff];
            ulonglong2 u01 = *(const ulonglong2*)up;
            ulonglong2 u23 = *(const ulonglong2*)(up + 4);
            ull h0 = splat2(hv.x);
            ull h1 = splat2(hv.y);
            ull h2 = splat2(hv.z);
            ull h3 = splat2(hv.w);
            fma2(acc[0],  u01.x, h0); fma2(acc[1],  u01.y, h0);
            fma2(acc[2],  u23.x, h0); fma2(acc[3],  u23.y, h0);
            fma2(acc[4],  u01.x, h1); fma2(acc[5],  u01.y, h1);
            fma2(acc[6],  u23.x, h1); fma2(acc[7],  u23.y, h1);
            fma2(acc[8],  u01.x, h2); fma2(acc[9],  u01.y, h2);
            fma2(acc[10], u23.x, h2); fma2(acc[11], u23.y, h2);
            fma2(acc[12], u01.x, h3); fma2(acc[13], u01.y, h3);
            fma2(acc[14], u23.x, h3); fma2(acc[15], u23.y, h3);
        }

        {
            ulonglong2* zw = zq + (w << 3) * 32 + ln;
#pragma unroll
            for (int bq = 0; bq < 4; ++bq) {
                zw[(((bq << 1) + 0) << 5)] =
                    make_ulonglong2(acc[(bq << 2) + 0], acc[(bq << 2) + 1]);
                zw[(((bq << 1) + 1) << 5)] =
                    make_ulonglong2(acc[(bq << 2) + 2], acc[(bq << 2) + 3]);
            }
        }
        __syncthreads();

        if (tid < 256) {
            ull s0 = 0ull;
            ull s1 = 0ull;
            const ulonglong2* zp = zq + (jr << 5) + ln;
#pragma unroll
            for (int wi = 0; wi < 16; ++wi) {
                ulonglong2 v = zp[wi << 8];
                add2(s0, v.x);
                add2(s1, v.y);
            }
            float zi, zf, zg, zo;
            unpack2(s0, zi, zf);
            unpack2(s1, zg, zo);
            zi += xpi;
            zf += xpf;
            zg += xpg;
            zo += xpo;

            float ig = 1.0f / (1.0f + __expf(-zi));
            float fg = 1.0f / (1.0f + __expf(-zf));
            float gv = 1.0f - 2.0f / (1.0f + __expf(2.0f * zg));
            float og = 1.0f / (1.0f + __expf(-zo));

            creg = fg * creg + ig * gv;
            float tanc = 1.0f - 2.0f / (1.0f + __expf(2.0f * creg));
            float hout = og * tanc;

            g_h[cur ^ 1][(ug << 5) + bf] = hout;
            outp[(((size_t)((bf << 9) | t)) << 10) + ug] = hout;
        }

        if (t < TT - 1) {
            __syncthreads();
            if (tid == 0) {
                asm volatile("red.release.gpu.global.add.u32 [%0], %1;"
                             :: "l"(&g_bar), "r"(1u) : "memory");
                const unsigned target = (unsigned)(t + 1) * NB;
                unsigned v;
                unsigned spins = 0;
                do {
                    asm volatile("ld.acquire.gpu.global.u32 %0, [%1];"
                                 : "=r"(v) : "l"(&g_bar) : "memory");
                } while (v < target && ++spins < 0x40000000u);
            }
            __syncthreads();
        }
    }
}

// ========================= launcher ======================================
extern "C" void kernel_launch(void* const* d_in, const int* in_sizes, int n_in,
                              void* d_out, int out_size) {
    const float* inputs = (const float*)d_in[0];
    const float* W      = (const float*)d_in[1];
    const float* U      = (const float*)d_in[2];
    const float* bias   = (const float*)d_in[3];
    float* outp = (float*)d_out;

    cudaFuncSetAttribute(lstm_kernel,
                         cudaFuncAttributeMaxDynamicSharedMemorySize, LSTM_SMEM);

    init_kernel<<<64, 256>>>();
    split_kernel<<<256, 256>>>(inputs, W);
    dim3 g1(32, 128);
    xproj_mma<<<g1, 256>>>(bias);
    lstm_kernel<<<NB, 512, LSTM_SMEM>>>(U, outp);
}